// round 5
// baseline (speedup 1.0000x reference)
#include <cuda_runtime.h>
#include <math_constants.h>
#include <cstdint>

#define B 4
#define NH 32
#define HD 128
#define HID 4096
#define S_PAST 8192
#define KV (S_PAST + 1)
#define HEAVY 2048
#define OUTL 16
#define BH (B * NH)

#define RSQRT_HD 0.08838834764831845f   // 1/sqrt(128)
#define RSQRT_OUTL 0.25f                // 1/sqrt(16)
#define FULLMASK 0xffffffffu

// ---------------- scratch (device globals; no allocation) ----------------
__device__ float g_qkv[3 * B * HID];     // pre-rope q,k,v
__device__ float g_q[BH * HD];           // roped q
__device__ float g_knew[BH * HD];        // roped k (appended position)
__device__ float g_vnew[BH * HD];        // v (appended position)
__device__ float g_gq[BH * OUTL];        // quantized gathered q
__device__ float g_attn[BH * KV];        // full attention logits
__device__ float g_gattn[BH * KV];       // label (quantized) logits
__device__ unsigned int g_mu[BH];        // flipped-uint running max of attn
__device__ float g_kth[BH];
__device__ float g_invZ[BH];
__device__ float g_hout[B * HID];        // per-head outputs, (b, h*HD+d)

__device__ __forceinline__ unsigned int fflip(float f) {
    unsigned int u = __float_as_uint(f);
    return (u & 0x80000000u) ? ~u : (u | 0x80000000u);
}
__device__ __forceinline__ float funflip(unsigned int u) {
    return __uint_as_float((u & 0x80000000u) ? (u & 0x7FFFFFFFu) : ~u);
}

// ---------------- K1: fused QKV GEMV ----------------
__global__ void qkv_gemv_kernel(const float* __restrict__ hid,
                                const float* __restrict__ Wq,
                                const float* __restrict__ Wk,
                                const float* __restrict__ Wv) {
    int t = blockIdx.x;
    int which = t >> 12;           // HID = 4096 = 2^12
    int row = t & (HID - 1);
    const float* W = (which == 0) ? Wq : (which == 1) ? Wk : Wv;
    const float4* w4 = reinterpret_cast<const float4*>(W + (size_t)row * HID);
    const float4* h4 = reinterpret_cast<const float4*>(hid);

    float a0 = 0.f, a1 = 0.f, a2 = 0.f, a3 = 0.f;
#pragma unroll 4
    for (int i = threadIdx.x; i < HID / 4; i += 128) {
        float4 w = __ldg(&w4[i]);
        float4 h;
        h = h4[i];
        a0 += w.x * h.x + w.y * h.y + w.z * h.z + w.w * h.w;
        h = h4[i + (HID / 4)];
        a1 += w.x * h.x + w.y * h.y + w.z * h.z + w.w * h.w;
        h = h4[i + 2 * (HID / 4)];
        a2 += w.x * h.x + w.y * h.y + w.z * h.z + w.w * h.w;
        h = h4[i + 3 * (HID / 4)];
        a3 += w.x * h.x + w.y * h.y + w.z * h.z + w.w * h.w;
    }
#pragma unroll
    for (int o = 16; o; o >>= 1) {
        a0 += __shfl_down_sync(FULLMASK, a0, o);
        a1 += __shfl_down_sync(FULLMASK, a1, o);
        a2 += __shfl_down_sync(FULLMASK, a2, o);
        a3 += __shfl_down_sync(FULLMASK, a3, o);
    }
    __shared__ float s[4][4];
    int warp = threadIdx.x >> 5, lane = threadIdx.x & 31;
    if (lane == 0) { s[warp][0] = a0; s[warp][1] = a1; s[warp][2] = a2; s[warp][3] = a3; }
    __syncthreads();
    if (threadIdx.x < 4) {
        float sum = s[0][threadIdx.x] + s[1][threadIdx.x] + s[2][threadIdx.x] + s[3][threadIdx.x];
        g_qkv[((size_t)which * B + threadIdx.x) * HID + row] = sum;
    }
}

// ---------------- K2: RoPE + gq quantization + init accumulators ----------------
__global__ void rope_kernel(const float* __restrict__ cosp,
                            const float* __restrict__ sinp,
                            const int* __restrict__ schan) {
    int bh = blockIdx.x;
    int b = bh >> 5, h = bh & 31;
    int d = threadIdx.x;

    g_hout[bh * HD + d] = 0.f;     // zero accumulator for K5 atomics
    if (d == 0) g_mu[bh] = 0u;     // flipped -inf for attn max

    float q = g_qkv[(0 * B + b) * HID + h * HD + d];
    float k = g_qkv[(1 * B + b) * HID + h * HD + d];
    float v = g_qkv[(2 * B + b) * HID + h * HD + d];
    float c = cosp[b * HD + d];
    float sn = sinp[b * HD + d];

    __shared__ float sq[HD], sk[HD], sqr[HD];
    sq[d] = q; sk[d] = k;
    __syncthreads();
    float rq = (d < HD / 2) ? -sq[d + HD / 2] : sq[d - HD / 2];
    float rk = (d < HD / 2) ? -sk[d + HD / 2] : sk[d - HD / 2];
    float qr = q * c + rq * sn;
    float kr = k * c + rk * sn;
    g_q[bh * HD + d] = qr;
    g_knew[bh * HD + d] = kr;
    g_vnew[bh * HD + d] = v;
    sqr[d] = qr;
    __syncthreads();

    if (d < 32) {
        float val = 0.f;
        if (d < OUTL) val = sqr[schan[h * HD + d]];
        float mn = (d < OUTL) ? val : CUDART_INF_F;
        float mx = (d < OUTL) ? val : -CUDART_INF_F;
#pragma unroll
        for (int o = 16; o; o >>= 1) {
            mn = fminf(mn, __shfl_xor_sync(FULLMASK, mn, o));
            mx = fmaxf(mx, __shfl_xor_sync(FULLMASK, mx, o));
        }
        float range = mx - mn;
        if (range == 0.f) range = 1.f;
        float scale = 15.f / range;
        float qq = fminf(fmaxf(rintf((val - mn) * scale), 0.f), 15.f);
        float deq = qq / scale + mn;
        if (d < OUTL) g_gq[bh * OUTL + d] = deq;
    }
}

// ---------------- K3: attn + gattn, thread-pair-per-row via smem staging ----
// 128 threads, 64 rows/block. Row stride 140 floats (16B-aligned); halves
// stored at +0 and +68 (both 16B-aligned offsets).
#define KSTRIDE 140
__global__ void attn_kernel(const float* __restrict__ pk,
                            const int* __restrict__ schan) {
    __shared__ float skr[64][KSTRIDE];   // 35.8 KB
    __shared__ float sq[HD];
    __shared__ float sgq[OUTL];
    __shared__ int sch[OUTL];
    __shared__ float swmax[4];

    int bh = blockIdx.y;
    int h = bh & 31;
    int tid = threadIdx.x;
    int base = blockIdx.x * 64;

    if (tid < HD) sq[tid] = g_q[bh * HD + tid];
    if (tid < OUTL) { sgq[tid] = g_gq[bh * OUTL + tid]; sch[tid] = schan[h * HD + tid]; }

    // ---- coalesced stage of 64 rows (512B each) into padded smem ----
#pragma unroll
    for (int i = 0; i < 16; i++) {
        int r = 4 * i + (tid >> 5);
        int j = base + r;
        int col = (tid & 31) * 4;
        int colp = col + (col >= 64 ? 4 : 0);
        if (j < S_PAST) {
            float4 v = __ldg(reinterpret_cast<const float4*>(pk + ((size_t)bh * S_PAST + j) * HD + col));
            *reinterpret_cast<float4*>(&skr[r][colp]) = v;
        } else if (j == S_PAST) {
            float4 v = *reinterpret_cast<const float4*>(g_knew + (size_t)bh * HD + col);
            *reinterpret_cast<float4*>(&skr[r][colp]) = v;
        }
    }
    __syncthreads();

    int r = tid >> 1;
    int hh = tid & 1;
    int j = base + r;
    bool valid = (j < KV);

    // ---- dot over this thread's 64-column half ----
    float d0 = 0.f, d1 = 0.f;
    {
        const float* row = &skr[r][68 * hh];
        const float* qq = &sq[64 * hh];
#pragma unroll
        for (int i = 0; i < 8; i++) {
            float4 kv = *reinterpret_cast<const float4*>(row + 8 * i);
            float4 qv = *reinterpret_cast<const float4*>(qq + 8 * i);
            d0 += kv.x * qv.x + kv.y * qv.y + kv.z * qv.z + kv.w * qv.w;
            float4 kw = *reinterpret_cast<const float4*>(row + 8 * i + 4);
            float4 qw = *reinterpret_cast<const float4*>(qq + 8 * i + 4);
            d1 += kw.x * qw.x + kw.y * qw.y + kw.z * qw.z + kw.w * qw.w;
        }
    }
    float dot = d0 + d1;
    dot += __shfl_xor_sync(FULLMASK, dot, 1);

    // ---- 8 gathered channels per thread, in-thread min/max ----
    float gk[8];
    float mn = CUDART_INF_F, mx = -CUDART_INF_F;
#pragma unroll
    for (int i = 0; i < 8; i++) {
        int c = sch[8 * hh + i];
        float v = skr[r][c + (c >= 64 ? 4 : 0)];
        gk[i] = v;
        mn = fminf(mn, v);
        mx = fmaxf(mx, v);
    }
    mn = fminf(mn, __shfl_xor_sync(FULLMASK, mn, 1));
    mx = fmaxf(mx, __shfl_xor_sync(FULLMASK, mx, 1));
    float range = mx - mn;
    if (range == 0.f) range = 1.f;
    float scale = 15.f / range;
    float p = 0.f;
#pragma unroll
    for (int i = 0; i < 8; i++) {
        float dq = fminf(fmaxf(rintf((gk[i] - mn) * scale), 0.f), 15.f) / scale + mn;
        p += sgq[8 * hh + i] * dq;
    }
    p += __shfl_xor_sync(FULLMASK, p, 1);

    float a = dot * RSQRT_HD;
    if (valid && hh == 0) {
        g_attn[(size_t)bh * KV + j] = a;
        g_gattn[(size_t)bh * KV + j] = p * RSQRT_OUTL;
    }

    // ---- block max of a -> global atomicMax (softmax shift constant) ----
    float am = (valid && hh == 0) ? a : -CUDART_INF_F;
#pragma unroll
    for (int o = 16; o; o >>= 1) am = fmaxf(am, __shfl_xor_sync(FULLMASK, am, o));
    int warp = tid >> 5, lane = tid & 31;
    if (lane == 0) swmax[warp] = am;
    __syncthreads();
    if (tid == 0) {
        float bm = fmaxf(fmaxf(swmax[0], swmax[1]), fmaxf(swmax[2], swmax[3]));
        if (bm > -CUDART_INF_F) atomicMax(&g_mu[bh], fflip(bm));
    }
}

// ---------------- K4: radix-select kth + masked softmax sum ----------------
#define ST 512                 // threads
#define NC 8                   // privatized hist copies (2 warps/copy)
__global__ void select_kernel() {
    __shared__ unsigned int skey[KV];        // 32772 B
    __shared__ unsigned int hist[NC][256];   // 8192 B
    __shared__ float sred[ST / 32];
    __shared__ unsigned int s_prefix, s_k;

    int bh = blockIdx.x;
    int tid = threadIdx.x;
    int warp = tid >> 5, lane = tid & 31;
    int copy = warp >> 1;

    for (int j = tid; j < KV; j += ST) {
        skey[j] = fflip(g_gattn[(size_t)bh * KV + j]);
    }
    if (tid == 0) { s_prefix = 0u; s_k = HEAVY; }
    __syncthreads();

#pragma unroll
    for (int pass = 0; pass < 4; pass++) {
        int shift = 24 - 8 * pass;
        for (int i = tid; i < NC * 256; i += ST) ((unsigned int*)hist)[i] = 0u;
        __syncthreads();
        unsigned int pfx = s_prefix;
        unsigned int k0 = s_k;
        unsigned int pmask = (pass == 0) ? 0u : (0xFFFFFFFFu << (shift + 8));

        for (int base = 0; base < KV; base += ST) {
            int j = base + tid;
            bool inb = (j < KV);
            unsigned int u = inb ? skey[j] : 0u;
            bool active = inb && ((u & pmask) == pfx);
            unsigned int bin = (u >> shift) & 255u;
            unsigned int act = __ballot_sync(FULLMASK, active);
            if (active) {
                unsigned int peers = __match_any_sync(act, bin);
                int leader = __ffs(peers) - 1;
                if (lane == leader)
                    atomicAdd(&hist[copy][bin], __popc(peers));
            }
        }
        __syncthreads();

        // warp 0 alone: reduce copies + suffix-select (no block barriers inside)
        if (warp == 0) {
            unsigned int cnt[8];
            unsigned int tot = 0u;
#pragma unroll
            for (int i = 0; i < 8; i++) {
                unsigned int c = 0u;
#pragma unroll
                for (int cc = 0; cc < NC; cc++) c += hist[cc][lane * 8 + i];
                cnt[i] = c;
                tot += c;
            }
            // inclusive suffix scan over lanes
            unsigned int s = tot;
#pragma unroll
            for (int o = 1; o < 32; o <<= 1) {
                unsigned int v = __shfl_down_sync(FULLMASK, s, o);
                if (lane + o < 32) s += v;
            }
            unsigned int higher = s - tot;       // keys in bins of higher lanes
            if (higher < k0 && higher + tot >= k0) {
                unsigned int run = higher;
#pragma unroll
                for (int i = 7; i >= 0; i--) {
                    run += cnt[i];
                    if (run >= k0) {
                        s_prefix = pfx | ((unsigned int)(lane * 8 + i) << shift);
                        s_k = k0 - (run - cnt[i]);
                        break;
                    }
                }
            }
        }
        __syncthreads();
    }

    unsigned int kkey = s_prefix;
    float kth = funflip(kkey);
    float m = funflip(g_mu[bh]);

    // masked sum of exp (shift by global max m; softmax is shift-invariant)
    float z = 0.f;
    for (int j = tid; j < KV; j += ST)
        if (skey[j] >= kkey) z += expf(g_attn[(size_t)bh * KV + j] - m);
#pragma unroll
    for (int o = 16; o; o >>= 1) z += __shfl_xor_sync(FULLMASK, z, o);
    if (lane == 0) sred[warp] = z;
    __syncthreads();
    if (tid == 0) {
        float t = 0.f;
#pragma unroll
        for (int w = 0; w < ST / 32; w++) t += sred[w];
        g_kth[bh] = kth;
        g_invZ[bh] = 1.f / t;
    }
}

// ---------------- K5: selective weighted value accumulation (split 32x) ----
__global__ void outv_kernel(const float* __restrict__ pv) {
    int bh = blockIdx.y;
    int tid = threadIdx.x;
    int warp = tid >> 5, lane = tid & 31;
    float kth = g_kth[bh], m = funflip(g_mu[bh]), invZ = g_invZ[bh];

    float4 acc = make_float4(0.f, 0.f, 0.f, 0.f);
    // 32 blocks x 8 warps = 256 warps stride over KV
    for (int j = blockIdx.x * 8 + warp; j < KV; j += 256) {
        float g = g_gattn[(size_t)bh * KV + j];
        if (g >= kth) {
            float w = expf(g_attn[(size_t)bh * KV + j] - m) * invZ;
            const float* vrow = (j < S_PAST)
                ? pv + ((size_t)bh * S_PAST + j) * HD
                : g_vnew + (size_t)bh * HD;
            float4 v4 = __ldg(&reinterpret_cast<const float4*>(vrow)[lane]);
            acc.x += w * v4.x; acc.y += w * v4.y; acc.z += w * v4.z; acc.w += w * v4.w;
        }
    }
    __shared__ float sacc[8][HD];
    reinterpret_cast<float4*>(&sacc[warp][0])[lane] = acc;
    __syncthreads();
    if (tid < HD) {
        float s = 0.f;
#pragma unroll
        for (int w = 0; w < 8; w++) s += sacc[w][tid];
        atomicAdd(&g_hout[bh * HD + tid], s);
    }
}

// ---------------- K6: output GEMV (hout @ Wo^T) ----------------
__global__ void out_gemv_kernel(const float* __restrict__ Wo,
                                float* __restrict__ out) {
    int row = blockIdx.x;
    const float4* w4 = reinterpret_cast<const float4*>(Wo + (size_t)row * HID);
    const float4* h4 = reinterpret_cast<const float4*>(g_hout);

    float a0 = 0.f, a1 = 0.f, a2 = 0.f, a3 = 0.f;
#pragma unroll 4
    for (int i = threadIdx.x; i < HID / 4; i += 128) {
        float4 w = __ldg(&w4[i]);
        float4 h;
        h = h4[i];
        a0 += w.x * h.x + w.y * h.y + w.z * h.z + w.w * h.w;
        h = h4[i + (HID / 4)];
        a1 += w.x * h.x + w.y * h.y + w.z * h.z + w.w * h.w;
        h = h4[i + 2 * (HID / 4)];
        a2 += w.x * h.x + w.y * h.y + w.z * h.z + w.w * h.w;
        h = h4[i + 3 * (HID / 4)];
        a3 += w.x * h.x + w.y * h.y + w.z * h.z + w.w * h.w;
    }
#pragma unroll
    for (int o = 16; o; o >>= 1) {
        a0 += __shfl_down_sync(FULLMASK, a0, o);
        a1 += __shfl_down_sync(FULLMASK, a1, o);
        a2 += __shfl_down_sync(FULLMASK, a2, o);
        a3 += __shfl_down_sync(FULLMASK, a3, o);
    }
    __shared__ float s[4][4];
    int warp = threadIdx.x >> 5, lane = threadIdx.x & 31;
    if (lane == 0) { s[warp][0] = a0; s[warp][1] = a1; s[warp][2] = a2; s[warp][3] = a3; }
    __syncthreads();
    if (threadIdx.x < 4) {
        float sum = s[0][threadIdx.x] + s[1][threadIdx.x] + s[2][threadIdx.x] + s[3][threadIdx.x];
        out[(size_t)threadIdx.x * HID + row] = sum;
    }
}

// ---------------- launch ----------------
extern "C" void kernel_launch(void* const* d_in, const int* in_sizes, int n_in,
                              void* d_out, int out_size) {
    const float* hid  = (const float*)d_in[0];
    const float* pk   = (const float*)d_in[1];
    const float* pv   = (const float*)d_in[2];
    const float* cosp = (const float*)d_in[3];
    const float* sinp = (const float*)d_in[4];
    const int*   sch  = (const int*)d_in[5];
    const float* Wq   = (const float*)d_in[6];
    const float* Wk   = (const float*)d_in[7];
    const float* Wv   = (const float*)d_in[8];
    const float* Wo   = (const float*)d_in[9];
    float* out = (float*)d_out;

    qkv_gemv_kernel<<<3 * HID, 128>>>(hid, Wq, Wk, Wv);
    rope_kernel<<<BH, 128>>>(cosp, sinp, sch);
    attn_kernel<<<dim3((KV + 63) / 64, BH), 128>>>(pk, sch);
    select_kernel<<<BH, ST>>>();
    outv_kernel<<<dim3(32, BH), 256>>>(pv);
    out_gemv_kernel<<<HID, 128>>>(Wo, out);
}

// round 7
// speedup vs baseline: 1.0494x; 1.0494x over previous
#include <cuda_runtime.h>
#include <math_constants.h>
#include <cstdint>

#define B 4
#define NH 32
#define HD 128
#define HID 4096
#define S_PAST 8192
#define KV (S_PAST + 1)
#define HEAVY 2048
#define OUTL 16
#define BH (B * NH)

#define RSQRT_HD 0.08838834764831845f   // 1/sqrt(128)
#define RSQRT_OUTL 0.25f                // 1/sqrt(16)
#define FULLMASK 0xffffffffu

// ---------------- scratch (device globals; no allocation) ----------------
__device__ float g_qkv[3 * B * HID];     // pre-rope q,k,v
__device__ float g_q[BH * HD];           // roped q
__device__ float g_knew[BH * HD];        // roped k (appended position)
__device__ float g_vnew[BH * HD];        // v (appended position)
__device__ float g_gq[BH * OUTL];        // quantized gathered q
__device__ float g_attn[BH * KV];        // full attention logits
__device__ float g_gattn[BH * KV];       // label (quantized) logits
__device__ unsigned int g_mu[BH];        // flipped-uint running max of attn
__device__ float g_kth[BH];
__device__ float g_z[BH];                // softmax denominator (unnormalized)
__device__ float g_hout[B * HID];        // per-head outputs (un-normalized)

__device__ __forceinline__ unsigned int fflip(float f) {
    unsigned int u = __float_as_uint(f);
    return (u & 0x80000000u) ? ~u : (u | 0x80000000u);
}
__device__ __forceinline__ float funflip(unsigned int u) {
    return __uint_as_float((u & 0x80000000u) ? (u & 0x7FFFFFFFu) : ~u);
}

// ---------------- K1: fused QKV GEMV ----------------
__global__ void qkv_gemv_kernel(const float* __restrict__ hid,
                                const float* __restrict__ Wq,
                                const float* __restrict__ Wk,
                                const float* __restrict__ Wv) {
    int t = blockIdx.x;
    int which = t >> 12;           // HID = 4096 = 2^12
    int row = t & (HID - 1);
    const float* W = (which == 0) ? Wq : (which == 1) ? Wk : Wv;
    const float4* w4 = reinterpret_cast<const float4*>(W + (size_t)row * HID);
    const float4* h4 = reinterpret_cast<const float4*>(hid);

    float a0 = 0.f, a1 = 0.f, a2 = 0.f, a3 = 0.f;
#pragma unroll 4
    for (int i = threadIdx.x; i < HID / 4; i += 128) {
        float4 w = __ldg(&w4[i]);
        float4 h;
        h = h4[i];
        a0 += w.x * h.x + w.y * h.y + w.z * h.z + w.w * h.w;
        h = h4[i + (HID / 4)];
        a1 += w.x * h.x + w.y * h.y + w.z * h.z + w.w * h.w;
        h = h4[i + 2 * (HID / 4)];
        a2 += w.x * h.x + w.y * h.y + w.z * h.z + w.w * h.w;
        h = h4[i + 3 * (HID / 4)];
        a3 += w.x * h.x + w.y * h.y + w.z * h.z + w.w * h.w;
    }
#pragma unroll
    for (int o = 16; o; o >>= 1) {
        a0 += __shfl_down_sync(FULLMASK, a0, o);
        a1 += __shfl_down_sync(FULLMASK, a1, o);
        a2 += __shfl_down_sync(FULLMASK, a2, o);
        a3 += __shfl_down_sync(FULLMASK, a3, o);
    }
    __shared__ float s[4][4];
    int warp = threadIdx.x >> 5, lane = threadIdx.x & 31;
    if (lane == 0) { s[warp][0] = a0; s[warp][1] = a1; s[warp][2] = a2; s[warp][3] = a3; }
    __syncthreads();
    if (threadIdx.x < 4) {
        float sum = s[0][threadIdx.x] + s[1][threadIdx.x] + s[2][threadIdx.x] + s[3][threadIdx.x];
        g_qkv[((size_t)which * B + threadIdx.x) * HID + row] = sum;
    }
}

// ---------------- K2: RoPE + gq quantization + init accumulators ----------------
__global__ void rope_kernel(const float* __restrict__ cosp,
                            const float* __restrict__ sinp,
                            const int* __restrict__ schan) {
    int bh = blockIdx.x;
    int b = bh >> 5, h = bh & 31;
    int d = threadIdx.x;

    g_hout[bh * HD + d] = 0.f;     // zero accumulator for K5 atomics
    if (d == 0) { g_mu[bh] = 0u; g_z[bh] = 0.f; }

    float q = g_qkv[(0 * B + b) * HID + h * HD + d];
    float k = g_qkv[(1 * B + b) * HID + h * HD + d];
    float v = g_qkv[(2 * B + b) * HID + h * HD + d];
    float c = cosp[b * HD + d];
    float sn = sinp[b * HD + d];

    __shared__ float sq[HD], sk[HD], sqr[HD];
    sq[d] = q; sk[d] = k;
    __syncthreads();
    float rq = (d < HD / 2) ? -sq[d + HD / 2] : sq[d - HD / 2];
    float rk = (d < HD / 2) ? -sk[d + HD / 2] : sk[d - HD / 2];
    float qr = q * c + rq * sn;
    float kr = k * c + rk * sn;
    g_q[bh * HD + d] = qr;
    g_knew[bh * HD + d] = kr;
    g_vnew[bh * HD + d] = v;
    sqr[d] = qr;
    __syncthreads();

    if (d < 32) {
        float val = 0.f;
        if (d < OUTL) val = sqr[schan[h * HD + d]];
        float mn = (d < OUTL) ? val : CUDART_INF_F;
        float mx = (d < OUTL) ? val : -CUDART_INF_F;
#pragma unroll
        for (int o = 16; o; o >>= 1) {
            mn = fminf(mn, __shfl_xor_sync(FULLMASK, mn, o));
            mx = fmaxf(mx, __shfl_xor_sync(FULLMASK, mx, o));
        }
        float range = mx - mn;
        if (range == 0.f) range = 1.f;
        float scale = 15.f / range;
        float qq = fminf(fmaxf(rintf((val - mn) * scale), 0.f), 15.f);
        float deq = qq / scale + mn;
        if (d < OUTL) g_gq[bh * OUTL + d] = deq;
    }
}

// ---------------- K3: attn + gattn, 4 threads per K row ----------------
// 256 threads = 8 warps; each warp handles 8 rows (lane = rowg*4 + seg).
// All reductions are 4-lane (2 shfl_xor), one instruction serves 8 rows.
__global__ void attn_kernel(const float* __restrict__ pk,
                            const int* __restrict__ schan) {
    __shared__ float sq[HD];
    __shared__ float sgq[OUTL];
    __shared__ int sch[OUTL];
    __shared__ float swmax[8];
    int bh = blockIdx.y;
    int h = bh & 31;
    int tid = threadIdx.x;
    if (tid < HD) sq[tid] = g_q[bh * HD + tid];
    if (tid < OUTL) { sgq[tid] = g_gq[bh * OUTL + tid]; sch[tid] = schan[h * HD + tid]; }
    __syncthreads();

    int warp = tid >> 5, lane = tid & 31;
    int rowg = lane >> 2;          // 0..7
    int seg = lane & 3;            // 0..3 (32-column segment)

    int j = blockIdx.x * 64 + warp * 8 + rowg;
    int jc = (j < KV) ? j : KV - 1;
    const float* krow = (jc < S_PAST) ? pk + ((size_t)bh * S_PAST + jc) * HD
                                      : g_knew + (size_t)bh * HD;

    // ---- 32-column segment dot: 8 float4 loads, MLP=8 ----
    const float4* kp = reinterpret_cast<const float4*>(krow + seg * 32);
    const float4* qp = reinterpret_cast<const float4*>(sq + seg * 32);
    float4 kr[8];
#pragma unroll
    for (int i = 0; i < 8; i++) kr[i] = __ldg(&kp[i]);

    // ---- 4 gathered channels per thread (L1 hits on the loaded row) ----
    float gk[4];
#pragma unroll
    for (int i = 0; i < 4; i++) gk[i] = __ldg(&krow[sch[seg * 4 + i]]);

    float d = 0.f;
#pragma unroll
    for (int i = 0; i < 8; i++) {
        float4 qv = qp[i];
        d = fmaf(kr[i].x, qv.x, fmaf(kr[i].y, qv.y,
            fmaf(kr[i].z, qv.z, fmaf(kr[i].w, qv.w, d))));
    }

    float mn = fminf(fminf(gk[0], gk[1]), fminf(gk[2], gk[3]));
    float mx = fmaxf(fmaxf(gk[0], gk[1]), fmaxf(gk[2], gk[3]));

    // ---- 4-lane reductions (2 shfl_xor each; butterfly broadcasts) ----
    d  += __shfl_xor_sync(FULLMASK, d, 1);
    d  += __shfl_xor_sync(FULLMASK, d, 2);
    mn = fminf(mn, __shfl_xor_sync(FULLMASK, mn, 1));
    mn = fminf(mn, __shfl_xor_sync(FULLMASK, mn, 2));
    mx = fmaxf(mx, __shfl_xor_sync(FULLMASK, mx, 1));
    mx = fmaxf(mx, __shfl_xor_sync(FULLMASK, mx, 2));

    float range = mx - mn;
    if (range == 0.f) range = 1.f;
    float scale = 15.f / range;
    float p = 0.f;
#pragma unroll
    for (int i = 0; i < 4; i++) {
        float dq = fminf(fmaxf(rintf((gk[i] - mn) * scale), 0.f), 15.f) / scale + mn;
        p += sgq[seg * 4 + i] * dq;
    }
    p += __shfl_xor_sync(FULLMASK, p, 1);
    p += __shfl_xor_sync(FULLMASK, p, 2);

    float a = d * RSQRT_HD;
    if (seg == 0 && j < KV) {
        g_attn[(size_t)bh * KV + j] = a;
        g_gattn[(size_t)bh * KV + j] = p * RSQRT_OUTL;
    }

    // ---- block max of a -> one atomicMax (softmax shift constant) ----
    float am = (seg == 0 && j < KV) ? a : -CUDART_INF_F;
#pragma unroll
    for (int o = 16; o; o >>= 1) am = fmaxf(am, __shfl_xor_sync(FULLMASK, am, o));
    if (lane == 0) swmax[warp] = am;
    __syncthreads();
    if (tid == 0) {
        float bm = swmax[0];
#pragma unroll
        for (int w = 1; w < 8; w++) bm = fmaxf(bm, swmax[w]);
        if (bm > -CUDART_INF_F) atomicMax(&g_mu[bh], fflip(bm));
    }
}

// ---------------- K4: radix-select kth largest gattn (radix only) ----------
#define ST 512                 // threads
#define NC 8                   // privatized hist copies (2 warps/copy)
__global__ void select_kernel() {
    __shared__ unsigned int skey[KV];        // 32772 B
    __shared__ unsigned int hist[NC][256];   // 8192 B
    __shared__ unsigned int s_prefix, s_k;

    int bh = blockIdx.x;
    int tid = threadIdx.x;
    int warp = tid >> 5, lane = tid & 31;
    int copy = warp >> 1;

    for (int j = tid; j < KV; j += ST) {
        skey[j] = fflip(g_gattn[(size_t)bh * KV + j]);
    }
    if (tid == 0) { s_prefix = 0u; s_k = HEAVY; }
    __syncthreads();

#pragma unroll
    for (int pass = 0; pass < 4; pass++) {
        int shift = 24 - 8 * pass;
        for (int i = tid; i < NC * 256; i += ST) ((unsigned int*)hist)[i] = 0u;
        __syncthreads();
        unsigned int pfx = s_prefix;
        unsigned int k0 = s_k;
        unsigned int pmask = (pass == 0) ? 0u : (0xFFFFFFFFu << (shift + 8));

        for (int base = 0; base < KV; base += ST) {
            int j = base + tid;
            bool inb = (j < KV);
            unsigned int u = inb ? skey[j] : 0u;
            bool active = inb && ((u & pmask) == pfx);
            unsigned int bin = (u >> shift) & 255u;
            unsigned int act = __ballot_sync(FULLMASK, active);
            if (active) {
                unsigned int peers = __match_any_sync(act, bin);
                int leader = __ffs(peers) - 1;
                if (lane == leader)
                    atomicAdd(&hist[copy][bin], __popc(peers));
            }
        }
        __syncthreads();

        // warp 0 alone: reduce copies + suffix-select (no block barriers inside)
        if (warp == 0) {
            unsigned int cnt[8];
            unsigned int tot = 0u;
#pragma unroll
            for (int i = 0; i < 8; i++) {
                unsigned int c = 0u;
#pragma unroll
                for (int cc = 0; cc < NC; cc++) c += hist[cc][lane * 8 + i];
                cnt[i] = c;
                tot += c;
            }
            // inclusive suffix scan over lanes
            unsigned int s = tot;
#pragma unroll
            for (int o = 1; o < 32; o <<= 1) {
                unsigned int v = __shfl_down_sync(FULLMASK, s, o);
                if (lane + o < 32) s += v;
            }
            unsigned int higher = s - tot;       // keys in bins of higher lanes
            if (higher < k0 && higher + tot >= k0) {
                unsigned int run = higher;
#pragma unroll
                for (int i = 7; i >= 0; i--) {
                    run += cnt[i];
                    if (run >= k0) {
                        s_prefix = pfx | ((unsigned int)(lane * 8 + i) << shift);
                        s_k = k0 - (run - cnt[i]);
                        break;
                    }
                }
            }
        }
        __syncthreads();
    }

    if (tid == 0) g_kth[bh] = funflip(s_prefix);
}

// ---------------- K5: selective weighted V accumulation + z sum (split 32x) ----
__global__ void outv_kernel(const float* __restrict__ pv) {
    int bh = blockIdx.y;
    int tid = threadIdx.x;
    int warp = tid >> 5, lane = tid & 31;
    float kth = g_kth[bh], m = funflip(g_mu[bh]);

    float4 acc = make_float4(0.f, 0.f, 0.f, 0.f);
    float z = 0.f;
    // 32 blocks x 8 warps = 256 warps stride over KV
    for (int j = blockIdx.x * 8 + warp; j < KV; j += 256) {
        float g = g_gattn[(size_t)bh * KV + j];
        if (g >= kth) {
            float w = __expf(g_attn[(size_t)bh * KV + j] - m);
            z += w;
            const float* vrow = (j < S_PAST)
                ? pv + ((size_t)bh * S_PAST + j) * HD
                : g_vnew + (size_t)bh * HD;
            float4 v4 = __ldg(&reinterpret_cast<const float4*>(vrow)[lane]);
            acc.x += w * v4.x; acc.y += w * v4.y; acc.z += w * v4.z; acc.w += w * v4.w;
        }
    }
    __shared__ float sacc[8][HD];
    __shared__ float sz[8];
    reinterpret_cast<float4*>(&sacc[warp][0])[lane] = acc;
    if (lane == 0) sz[warp] = z;   // z identical across lanes (uniform branch)
    __syncthreads();
    if (tid < HD) {
        float s = 0.f;
#pragma unroll
        for (int w = 0; w < 8; w++) s += sacc[w][tid];
        atomicAdd(&g_hout[bh * HD + tid], s);
    }
    if (tid == 0) {
        float t = 0.f;
#pragma unroll
        for (int w = 0; w < 8; w++) t += sz[w];
        atomicAdd(&g_z[bh], t);
    }
}

// ---------------- K6: output GEMV (normalize-by-z folded in) ----------------
__global__ void out_gemv_kernel(const float* __restrict__ Wo,
                                float* __restrict__ out) {
    __shared__ float sinv[BH];
    int tid = threadIdx.x;
    if (tid < BH) sinv[tid] = 1.f / g_z[tid];
    __syncthreads();

    int row = blockIdx.x;
    const float4* w4 = reinterpret_cast<const float4*>(Wo + (size_t)row * HID);
    const float4* h4 = reinterpret_cast<const float4*>(g_hout);

    float a0 = 0.f, a1 = 0.f, a2 = 0.f, a3 = 0.f;
#pragma unroll 4
    for (int i = tid; i < HID / 4; i += 128) {
        int hh = i >> 5;                 // head index 0..31
        float4 w = __ldg(&w4[i]);
        float4 h;
        float s;
        h = h4[i];                 s = sinv[hh];
        a0 += s * (w.x * h.x + w.y * h.y + w.z * h.z + w.w * h.w);
        h = h4[i + (HID / 4)];     s = sinv[32 + hh];
        a1 += s * (w.x * h.x + w.y * h.y + w.z * h.z + w.w * h.w);
        h = h4[i + 2 * (HID / 4)]; s = sinv[64 + hh];
        a2 += s * (w.x * h.x + w.y * h.y + w.z * h.z + w.w * h.w);
        h = h4[i + 3 * (HID / 4)]; s = sinv[96 + hh];
        a3 += s * (w.x * h.x + w.y * h.y + w.z * h.z + w.w * h.w);
    }
#pragma unroll
    for (int o = 16; o; o >>= 1) {
        a0 += __shfl_down_sync(FULLMASK, a0, o);
        a1 += __shfl_down_sync(FULLMASK, a1, o);
        a2 += __shfl_down_sync(FULLMASK, a2, o);
        a3 += __shfl_down_sync(FULLMASK, a3, o);
    }
    __shared__ float s[4][4];
    int warp = tid >> 5, lane = tid & 31;
    if (lane == 0) { s[warp][0] = a0; s[warp][1] = a1; s[warp][2] = a2; s[warp][3] = a3; }
    __syncthreads();
    if (tid < 4) {
        float sum = s[0][tid] + s[1][tid] + s[2][tid] + s[3][tid];
        out[(size_t)tid * HID + row] = sum;
    }
}

// ---------------- launch ----------------
extern "C" void kernel_launch(void* const* d_in, const int* in_sizes, int n_in,
                              void* d_out, int out_size) {
    const float* hid  = (const float*)d_in[0];
    const float* pk   = (const float*)d_in[1];
    const float* pv   = (const float*)d_in[2];
    const float* cosp = (const float*)d_in[3];
    const float* sinp = (const float*)d_in[4];
    const int*   sch  = (const int*)d_in[5];
    const float* Wq   = (const float*)d_in[6];
    const float* Wk   = (const float*)d_in[7];
    const float* Wv   = (const float*)d_in[8];
    const float* Wo   = (const float*)d_in[9];
    float* out = (float*)d_out;

    qkv_gemv_kernel<<<3 * HID, 128>>>(hid, Wq, Wk, Wv);
    rope_kernel<<<BH, 128>>>(cosp, sinp, sch);
    attn_kernel<<<dim3((KV + 63) / 64, BH), 256>>>(pk, sch);
    select_kernel<<<BH, ST>>>();
    outv_kernel<<<dim3(32, BH), 256>>>(pv);
    out_gemv_kernel<<<HID, 128>>>(Wo, out);
}